// round 5
// baseline (speedup 1.0000x reference)
#include <cuda_runtime.h>
#include <cuda_fp16.h>
#include <math.h>
#include <stdint.h>

// ---------------- problem constants ----------------
#define BATCH   4
#define NTOK    1024
#define EMBED   768
#define HEADS   12
#define HD      64
#define DEPTH   4
#define QKVC    2304
#define MLPD    3072
#define MTOT    4096
#define BH      48
#define RELT    63

// ---------------- scratch ----------------
__device__ float  g_h[MTOT * EMBED];
__device__ __half g_ln[MTOT * EMBED];
__device__ float  g_qkv[MTOT * QKVC];
__device__ __half g_attnout[MTOT * EMBED];
__device__ __half g_mlp[MTOT * MLPD];
__device__ float  g_relh[BH * NTOK * 32];
__device__ float  g_relw[BH * NTOK * 32];
__device__ __half g_col[MTOT * EMBED];
__device__ __half g_bth[MLPD * EMBED];   // transposed fp16 weights (max 3072x768)

// ---------------- helpers ----------------
__device__ __forceinline__ float gelu_exact(float x) {
    return 0.5f * x * (1.0f + erff(x * 0.70710678118654752440f));
}
__device__ __forceinline__ float blockSum256(float v, float* red) {
    const int tid = threadIdx.x;
    #pragma unroll
    for (int o = 16; o > 0; o >>= 1) v += __shfl_xor_sync(0xffffffffu, v, o);
    if ((tid & 31) == 0) red[tid >> 5] = v;
    __syncthreads();
    float t = 0.f;
    #pragma unroll
    for (int i = 0; i < 8; i++) t += red[i];
    return t;
}
__device__ __forceinline__ void mma_f16(float* d, const uint32_t* a,
                                        const uint32_t* b) {
    asm volatile(
        "mma.sync.aligned.m16n8k16.row.col.f32.f16.f16.f32 "
        "{%0,%1,%2,%3}, {%4,%5,%6,%7}, {%8,%9}, {%0,%1,%2,%3};\n"
        : "+f"(d[0]), "+f"(d[1]), "+f"(d[2]), "+f"(d[3])
        : "r"(a[0]), "r"(a[1]), "r"(a[2]), "r"(a[3]), "r"(b[0]), "r"(b[1]));
}

// ---------------- fp16 tensor GEMM: C[M,N] = A[M,K] * Bt[N,K]^T ------------
// 128x128 tile, BK=32, 8 warps (2x4), m16n8k16. A and Bt are fp16 K-major.
// EPI: 1 = +bias -> float C, 2 = +bias+res -> float C,
//      3 = gelu(+bias) -> half C, 4 = +bias+pos-broadcast -> float C
template <int EPI>
__global__ void __launch_bounds__(256) hgemm(
    int M, int N, int K,
    const __half* __restrict__ A, const __half* __restrict__ Bt,
    void* __restrict__ Cv,
    const float* __restrict__ bias, const float* __restrict__ res)
{
    constexpr int SK = 40;   // 32 + 8 pad halfs -> conflict-free frag reads
    __shared__ __half As[2][128][SK];
    __shared__ __half Bs[2][128][SK];

    const int tid = threadIdx.x;
    const int lane = tid & 31;
    const int wid = tid >> 5;
    const int wm = wid & 1;              // 64 rows
    const int wn = wid >> 1;             // 4 x 32 cols
    const int g = lane >> 2, tg = lane & 3;

    const __half* Ab = A + (size_t)blockIdx.y * 128 * K;
    const __half* Bb = Bt + (size_t)blockIdx.x * 128 * K;

    float acc[4][4][4];
    #pragma unroll
    for (int i = 0; i < 4; i++)
        #pragma unroll
        for (int j = 0; j < 4; j++)
            #pragma unroll
            for (int r = 0; r < 4; r++) acc[i][j][r] = 0.f;

    const int sr = tid >> 2;             // 0..63 (+64)
    const int sk = (tid & 3) * 8;        // half offset, 16B granules

    uint4 pa[2], pb[2];
    const int nIter = K / 32;

    #pragma unroll
    for (int p = 0; p < 2; p++) {
        pa[p] = *reinterpret_cast<const uint4*>(Ab + (size_t)(sr + p * 64) * K + sk);
        pb[p] = *reinterpret_cast<const uint4*>(Bb + (size_t)(sr + p * 64) * K + sk);
    }
    #pragma unroll
    for (int p = 0; p < 2; p++) {
        *reinterpret_cast<uint4*>(&As[0][sr + p * 64][sk]) = pa[p];
        *reinterpret_cast<uint4*>(&Bs[0][sr + p * 64][sk]) = pb[p];
    }
    __syncthreads();

    int buf = 0;
    for (int it = 0; it < nIter; ++it) {
        if (it + 1 < nIter) {
            const int k0 = (it + 1) * 32;
            #pragma unroll
            for (int p = 0; p < 2; p++) {
                pa[p] = *reinterpret_cast<const uint4*>(
                    Ab + (size_t)(sr + p * 64) * K + k0 + sk);
                pb[p] = *reinterpret_cast<const uint4*>(
                    Bb + (size_t)(sr + p * 64) * K + k0 + sk);
            }
        }
        #pragma unroll
        for (int kf = 0; kf < 2; kf++) {
            uint32_t af[4][4];
            uint32_t bf[4][2];
            #pragma unroll
            for (int mf = 0; mf < 4; mf++) {
                const int r = wm * 64 + mf * 16;
                af[mf][0] = *reinterpret_cast<const uint32_t*>(
                    &As[buf][r + g][kf * 16 + tg * 2]);
                af[mf][1] = *reinterpret_cast<const uint32_t*>(
                    &As[buf][r + 8 + g][kf * 16 + tg * 2]);
                af[mf][2] = *reinterpret_cast<const uint32_t*>(
                    &As[buf][r + g][kf * 16 + tg * 2 + 8]);
                af[mf][3] = *reinterpret_cast<const uint32_t*>(
                    &As[buf][r + 8 + g][kf * 16 + tg * 2 + 8]);
            }
            #pragma unroll
            for (int nf = 0; nf < 4; nf++) {
                const int c = wn * 32 + nf * 8;
                bf[nf][0] = *reinterpret_cast<const uint32_t*>(
                    &Bs[buf][c + g][kf * 16 + tg * 2]);
                bf[nf][1] = *reinterpret_cast<const uint32_t*>(
                    &Bs[buf][c + g][kf * 16 + tg * 2 + 8]);
            }
            #pragma unroll
            for (int mf = 0; mf < 4; mf++)
                #pragma unroll
                for (int nf = 0; nf < 4; nf++)
                    mma_f16(acc[mf][nf], af[mf], bf[nf]);
        }
        if (it + 1 < nIter) {
            #pragma unroll
            for (int p = 0; p < 2; p++) {
                *reinterpret_cast<uint4*>(&As[buf ^ 1][sr + p * 64][sk]) = pa[p];
                *reinterpret_cast<uint4*>(&Bs[buf ^ 1][sr + p * 64][sk]) = pb[p];
            }
        }
        __syncthreads();
        buf ^= 1;
    }

    float* Cf = (float*)Cv;
    __half* Ch = (__half*)Cv;
    #pragma unroll
    for (int mf = 0; mf < 4; mf++) {
        const int row0 = blockIdx.y * 128 + wm * 64 + mf * 16 + g;
        #pragma unroll
        for (int nf = 0; nf < 4; nf++) {
            const int col = blockIdx.x * 128 + wn * 32 + nf * 8 + tg * 2;
            #pragma unroll
            for (int half_ = 0; half_ < 2; half_++) {
                const int m = row0 + half_ * 8;
                float c0 = acc[mf][nf][half_ * 2 + 0];
                float c1 = acc[mf][nf][half_ * 2 + 1];
                if (EPI == 1) {
                    c0 += bias[col]; c1 += bias[col + 1];
                    *reinterpret_cast<float2*>(&Cf[(size_t)m * N + col]) =
                        make_float2(c0, c1);
                } else if (EPI == 2) {
                    c0 += bias[col]     + res[(size_t)m * N + col];
                    c1 += bias[col + 1] + res[(size_t)m * N + col + 1];
                    *reinterpret_cast<float2*>(&Cf[(size_t)m * N + col]) =
                        make_float2(c0, c1);
                } else if (EPI == 3) {
                    c0 = gelu_exact(c0 + bias[col]);
                    c1 = gelu_exact(c1 + bias[col + 1]);
                    *reinterpret_cast<__half2*>(&Ch[(size_t)m * N + col]) =
                        __floats2half2_rn(c0, c1);
                } else {  // EPI 4
                    c0 += bias[col]     + res[(size_t)(m & (NTOK - 1)) * N + col];
                    c1 += bias[col + 1] + res[(size_t)(m & (NTOK - 1)) * N + col + 1];
                    *reinterpret_cast<float2*>(&Cf[(size_t)m * N + col]) =
                        make_float2(c0, c1);
                }
            }
        }
    }
}

// ---------------- weight transpose+convert W[K][N] f32 -> WT[N][K] f16 -----
__global__ void __launch_bounds__(256) wtrans_h(const float* __restrict__ W,
                                                __half* __restrict__ WT,
                                                int K, int N)
{
    __shared__ float t[32][33];
    const int kb = blockIdx.x * 32, nb = blockIdx.y * 32;
    const int tx = threadIdx.x & 31, ty = threadIdx.x >> 5;
    #pragma unroll
    for (int i = 0; i < 32; i += 8)
        t[ty + i][tx] = W[(size_t)(kb + ty + i) * N + nb + tx];
    __syncthreads();
    #pragma unroll
    for (int i = 0; i < 32; i += 8)
        WT[(size_t)(nb + ty + i) * K + kb + tx] = __float2half_rn(t[tx][ty + i]);
}

// convert f32 [N][K] (already K-major) -> f16
__global__ void __launch_bounds__(256) conv_h(const float* __restrict__ W,
                                              __half* __restrict__ WT, int n)
{
    int idx = blockIdx.x * 256 + threadIdx.x;
    if (idx < n) WT[idx] = __float2half_rn(W[idx]);
}

// ---------------- im2col (f32 -> f16) ----------------
__global__ void __launch_bounds__(256) im2col_h(const float* __restrict__ x,
                                                __half* __restrict__ col)
{
    int idx = blockIdx.x * 256 + threadIdx.x;
    int m = idx / EMBED, k = idx - m * EMBED;
    int b = m >> 10;
    int gy = (m >> 5) & 31, gx = m & 31;
    int ci = k >> 8;
    int ph = (k >> 4) & 15, pw = k & 15;
    col[idx] = __float2half_rn(
        x[(((size_t)b * 3 + ci) * 512 + gy * 16 + ph) * 512 + gx * 16 + pw]);
}

// ---------------- LayerNorm (f32 in -> f16 out) ----------------
__global__ void __launch_bounds__(256) layernorm_h(
    const float* __restrict__ in, const float* __restrict__ w,
    const float* __restrict__ b, __half* __restrict__ out)
{
    __shared__ float red[8];
    const int tid = threadIdx.x;
    const float* p = in + (size_t)blockIdx.x * EMBED;
    __half* q = out + (size_t)blockIdx.x * EMBED;
    float x0 = p[tid], x1 = p[tid + 256], x2 = p[tid + 512];
    float s  = blockSum256(x0 + x1 + x2, red);
    __syncthreads();
    float sq = blockSum256(x0 * x0 + x1 * x1 + x2 * x2, red);
    float mean = s * (1.f / 768.f);
    float var = sq * (1.f / 768.f) - mean * mean;
    float rs = rsqrtf(var + 1e-5f);
    q[tid]       = __float2half_rn((x0 - mean) * rs * w[tid]       + b[tid]);
    q[tid + 256] = __float2half_rn((x1 - mean) * rs * w[tid + 256] + b[tid + 256]);
    q[tid + 512] = __float2half_rn((x2 - mean) * rs * w[tid + 512] + b[tid + 512]);
}

// ---------------- rel-pos bias tables ----------------
__global__ void __launch_bounds__(64) rel_tables_k(
    const float* __restrict__ qkv, const float* __restrict__ rph,
    const float* __restrict__ rpw, float* __restrict__ relh,
    float* __restrict__ relw)
{
    __shared__ float qv[HD];
    const int bq = blockIdx.x;
    const int bh = bq >> 10, q = bq & 1023;
    const int b = bh / HEADS, head = bh % HEADS;
    const int hq = q >> 5, wq = q & 31;
    const int tid = threadIdx.x;
    qv[tid] = qkv[((size_t)(b * NTOK + q)) * QKVC + head * HD + tid];
    __syncthreads();
    const int kidx = tid & 31;
    const float* r;
    float* out;
    if (tid < 32) { r = rph + (hq - kidx + 31) * HD; out = relh; }
    else          { r = rpw + (wq - kidx + 31) * HD; out = relw; }
    float s = 0.f;
    #pragma unroll
    for (int d = 0; d < HD; d++) s = fmaf(qv[d], r[d], s);
    out[((size_t)bh * NTOK + q) * 32 + kidx] = s;
}

// ---------------- fused flash attention (fp16 mma) ----------------
struct FlashSmem {
    __half Kh[64][72];   // [key][d]
    __half Vt[64][72];   // [d][key]  (transposed at staging)
    __half P[64][72];    // P tile (also Q staging at start)
    float  S[64][68];
    float  rh[64][32];
    float  rw[64][32];
    float  mrow[64];
    float  lrow[64];
    float  arow[64];
};

__global__ void __launch_bounds__(256) flash_attn_k(
    const float* __restrict__ qkv, const float* __restrict__ relh,
    const float* __restrict__ relw, __half* __restrict__ outbuf)
{
    extern __shared__ char smraw[];
    FlashSmem& sm = *reinterpret_cast<FlashSmem*>(smraw);
    const int qt = blockIdx.x, bh = blockIdx.y;
    const int b = bh / HEADS, head = bh % HEADS;
    const float* Qg = qkv + (size_t)b * NTOK * QKVC + head * HD;
    const float* Kg = Qg + EMBED;
    const float* Vg = Qg + 2 * EMBED;
    const int tid = threadIdx.x, lane = tid & 31, wid = tid >> 5;
    const int wm = wid & 3, wn = wid >> 2;
    const int g = lane >> 2, tg = lane & 3;

    for (int i = tid; i < 64 * 32; i += 256) {
        int r = i >> 5, c = i & 31;
        sm.rh[r][c] = relh[((size_t)bh * NTOK + qt * 64 + r) * 32 + c];
        sm.rw[r][c] = relw[((size_t)bh * NTOK + qt * 64 + r) * 32 + c];
    }
    if (tid < 64) { sm.mrow[tid] = -INFINITY; sm.lrow[tid] = 0.f; }

    // stage Q (f16) into P buffer, lift fragments to registers
    const int sKey = tid >> 4;           // 0..15 (+16r)
    const int sD4  = (tid & 15) * 4;     // 0..60
    #pragma unroll
    for (int r = 0; r < 4; r++) {
        float4 v = *reinterpret_cast<const float4*>(
            Qg + (size_t)(qt * 64 + sKey + 16 * r) * QKVC + sD4);
        *reinterpret_cast<__half2*>(&sm.P[sKey + 16 * r][sD4]) =
            __floats2half2_rn(v.x, v.y);
        *reinterpret_cast<__half2*>(&sm.P[sKey + 16 * r][sD4 + 2]) =
            __floats2half2_rn(v.z, v.w);
    }
    __syncthreads();
    uint32_t aq[4][4];
    #pragma unroll
    for (int kf = 0; kf < 4; kf++) {
        aq[kf][0] = *reinterpret_cast<const uint32_t*>(
            &sm.P[wm * 16 + g][kf * 16 + tg * 2]);
        aq[kf][1] = *reinterpret_cast<const uint32_t*>(
            &sm.P[wm * 16 + 8 + g][kf * 16 + tg * 2]);
        aq[kf][2] = *reinterpret_cast<const uint32_t*>(
            &sm.P[wm * 16 + g][kf * 16 + tg * 2 + 8]);
        aq[kf][3] = *reinterpret_cast<const uint32_t*>(
            &sm.P[wm * 16 + 8 + g][kf * 16 + tg * 2 + 8]);
    }

    float oacc[4][4];
    #pragma unroll
    for (int i = 0; i < 4; i++)
        #pragma unroll
        for (int j = 0; j < 4; j++) oacc[i][j] = 0.f;

    float4 pk[4], pv[4];
    #pragma unroll
    for (int r = 0; r < 4; r++) {
        pk[r] = *reinterpret_cast<const float4*>(
            Kg + (size_t)(sKey + 16 * r) * QKVC + sD4);
        pv[r] = *reinterpret_cast<const float4*>(
            Vg + (size_t)(sKey + 16 * r) * QKVC + sD4);
    }

    for (int t = 0; t < 16; t++) {
        __syncthreads();
        #pragma unroll
        for (int r = 0; r < 4; r++) {
            const int key = sKey + 16 * r;
            *reinterpret_cast<__half2*>(&sm.Kh[key][sD4]) =
                __floats2half2_rn(pk[r].x, pk[r].y);
            *reinterpret_cast<__half2*>(&sm.Kh[key][sD4 + 2]) =
                __floats2half2_rn(pk[r].z, pk[r].w);
            sm.Vt[sD4 + 0][key] = __float2half_rn(pv[r].x);
            sm.Vt[sD4 + 1][key] = __float2half_rn(pv[r].y);
            sm.Vt[sD4 + 2][key] = __float2half_rn(pv[r].z);
            sm.Vt[sD4 + 3][key] = __float2half_rn(pv[r].w);
        }
        __syncthreads();
        if (t + 1 < 16) {
            #pragma unroll
            for (int r = 0; r < 4; r++) {
                pk[r] = *reinterpret_cast<const float4*>(
                    Kg + (size_t)((t + 1) * 64 + sKey + 16 * r) * QKVC + sD4);
                pv[r] = *reinterpret_cast<const float4*>(
                    Vg + (size_t)((t + 1) * 64 + sKey + 16 * r) * QKVC + sD4);
            }
        }
        // ---- S = Q K^T ----
        float sacc[4][4];
        #pragma unroll
        for (int i = 0; i < 4; i++)
            #pragma unroll
            for (int j = 0; j < 4; j++) sacc[i][j] = 0.f;
        #pragma unroll
        for (int kf = 0; kf < 4; kf++) {
            uint32_t bf[4][2];
            #pragma unroll
            for (int nf = 0; nf < 4; nf++) {
                const int c = wn * 32 + nf * 8;
                bf[nf][0] = *reinterpret_cast<const uint32_t*>(
                    &sm.Kh[c + g][kf * 16 + tg * 2]);
                bf[nf][1] = *reinterpret_cast<const uint32_t*>(
                    &sm.Kh[c + g][kf * 16 + tg * 2 + 8]);
            }
            #pragma unroll
            for (int nf = 0; nf < 4; nf++) mma_f16(sacc[nf], aq[kf], bf[nf]);
        }
        #pragma unroll
        for (int nf = 0; nf < 4; nf++) {
            const int c = wn * 32 + nf * 8 + tg * 2;
            sm.S[wm * 16 + g][c]         = sacc[nf][0] * 0.125f;
            sm.S[wm * 16 + g][c + 1]     = sacc[nf][1] * 0.125f;
            sm.S[wm * 16 + 8 + g][c]     = sacc[nf][2] * 0.125f;
            sm.S[wm * 16 + 8 + g][c + 1] = sacc[nf][3] * 0.125f;
        }
        __syncthreads();
        // ---- online softmax (4 threads per row) ----
        {
            const int row = tid >> 2, part = tid & 3;
            const float mo = sm.mrow[row];
            const float rhv = sm.rh[row][(t << 1) + (part >> 1)];
            float vals[16];
            float tmax = -INFINITY;
            #pragma unroll
            for (int j = 0; j < 16; j++) {
                float s = sm.S[row][part * 16 + j] + rhv
                        + sm.rw[row][(part & 1) * 16 + j];
                vals[j] = s;
                tmax = fmaxf(tmax, s);
            }
            tmax = fmaxf(tmax, __shfl_xor_sync(0xffffffffu, tmax, 1));
            tmax = fmaxf(tmax, __shfl_xor_sync(0xffffffffu, tmax, 2));
            const float nm = fmaxf(mo, tmax);
            float lsum = 0.f;
            #pragma unroll
            for (int j = 0; j < 16; j += 2) {
                float p0 = expf(vals[j] - nm);
                float p1 = expf(vals[j + 1] - nm);
                lsum += p0 + p1;
                *reinterpret_cast<__half2*>(&sm.P[row][part * 16 + j]) =
                    __floats2half2_rn(p0, p1);
            }
            lsum += __shfl_xor_sync(0xffffffffu, lsum, 1);
            lsum += __shfl_xor_sync(0xffffffffu, lsum, 2);
            if (part == 0) {
                const float alpha = expf(mo - nm);
                sm.mrow[row] = nm;
                sm.lrow[row] = sm.lrow[row] * alpha + lsum;
                sm.arow[row] = alpha;
            }
        }
        __syncthreads();
        // ---- rescale O, accumulate O += P V ----
        const float a0 = sm.arow[wm * 16 + g];
        const float a1 = sm.arow[wm * 16 + 8 + g];
        #pragma unroll
        for (int nf = 0; nf < 4; nf++) {
            oacc[nf][0] *= a0; oacc[nf][1] *= a0;
            oacc[nf][2] *= a1; oacc[nf][3] *= a1;
        }
        #pragma unroll
        for (int kf = 0; kf < 4; kf++) {
            uint32_t ap[4];
            ap[0] = *reinterpret_cast<const uint32_t*>(
                &sm.P[wm * 16 + g][kf * 16 + tg * 2]);
            ap[1] = *reinterpret_cast<const uint32_t*>(
                &sm.P[wm * 16 + 8 + g][kf * 16 + tg * 2]);
            ap[2] = *reinterpret_cast<const uint32_t*>(
                &sm.P[wm * 16 + g][kf * 16 + tg * 2 + 8]);
            ap[3] = *reinterpret_cast<const uint32_t*>(
                &sm.P[wm * 16 + 8 + g][kf * 16 + tg * 2 + 8]);
            uint32_t bf[4][2];
            #pragma unroll
            for (int nf = 0; nf < 4; nf++) {
                const int c = wn * 32 + nf * 8;
                bf[nf][0] = *reinterpret_cast<const uint32_t*>(
                    &sm.Vt[c + g][kf * 16 + tg * 2]);
                bf[nf][1] = *reinterpret_cast<const uint32_t*>(
                    &sm.Vt[c + g][kf * 16 + tg * 2 + 8]);
            }
            #pragma unroll
            for (int nf = 0; nf < 4; nf++) mma_f16(oacc[nf], ap, bf[nf]);
        }
    }
    __syncthreads();
    const float li0 = 1.f / sm.lrow[wm * 16 + g];
    const float li1 = 1.f / sm.lrow[wm * 16 + 8 + g];
    const int m0 = qt * 64 + wm * 16 + g;
    #pragma unroll
    for (int nf = 0; nf < 4; nf++) {
        const int d = wn * 32 + nf * 8 + tg * 2;
        __half* dst0 = outbuf + ((size_t)b * NTOK + m0) * EMBED + head * HD + d;
        __half* dst1 = dst0 + 8 * EMBED;
        *reinterpret_cast<__half2*>(dst0) =
            __floats2half2_rn(oacc[nf][0] * li0, oacc[nf][1] * li0);
        *reinterpret_cast<__half2*>(dst1) =
            __floats2half2_rn(oacc[nf][2] * li1, oacc[nf][3] * li1);
    }
}

// ---------------- host launcher ----------------
extern "C" void kernel_launch(void* const* d_in, const int* in_sizes, int n_in,
                              void* d_out, int out_size)
{
    const float* x       = (const float*)d_in[0];
    const float* conv_w  = (const float*)d_in[1];
    const float* conv_b  = (const float*)d_in[2];
    const float* pos     = (const float*)d_in[3];
    const float* ln1_w   = (const float*)d_in[4];
    const float* ln1_b   = (const float*)d_in[5];
    const float* qkv_w   = (const float*)d_in[6];
    const float* qkv_b   = (const float*)d_in[7];
    const float* proj_w  = (const float*)d_in[8];
    const float* proj_b  = (const float*)d_in[9];
    const float* rph     = (const float*)d_in[10];
    const float* rpw     = (const float*)d_in[11];
    const float* ln2_w   = (const float*)d_in[12];
    const float* ln2_b   = (const float*)d_in[13];
    const float* fc1_w   = (const float*)d_in[14];
    const float* fc1_b   = (const float*)d_in[15];
    const float* fc2_w   = (const float*)d_in[16];
    const float* fc2_b   = (const float*)d_in[17];
    float* out = (float*)d_out;

    float *h, *qkv, *relh, *relw;
    __half *ln, *attnout, *mlp, *col, *bth;
    cudaGetSymbolAddress((void**)&h, g_h);
    cudaGetSymbolAddress((void**)&ln, g_ln);
    cudaGetSymbolAddress((void**)&qkv, g_qkv);
    cudaGetSymbolAddress((void**)&attnout, g_attnout);
    cudaGetSymbolAddress((void**)&mlp, g_mlp);
    cudaGetSymbolAddress((void**)&relh, g_relh);
    cudaGetSymbolAddress((void**)&relw, g_relw);
    cudaGetSymbolAddress((void**)&col, g_col);
    cudaGetSymbolAddress((void**)&bth, g_bth);

    cudaFuncSetAttribute(flash_attn_k,
                         cudaFuncAttributeMaxDynamicSharedMemorySize,
                         (int)sizeof(FlashSmem));

    // ---- patch embed ----
    conv_h<<<(EMBED * EMBED + 255) / 256, 256>>>(conv_w, bth, EMBED * EMBED);
    im2col_h<<<(MTOT * EMBED) / 256, 256>>>(x, col);
    hgemm<4><<<dim3(EMBED / 128, MTOT / 128), 256>>>(
        MTOT, EMBED, EMBED, col, bth, h, conv_b, pos);

    for (int L = 0; L < DEPTH; L++) {
        layernorm_h<<<MTOT, 256>>>(h, ln1_w + L * EMBED, ln1_b + L * EMBED, ln);
        wtrans_h<<<dim3(EMBED / 32, QKVC / 32), 256>>>(
            qkv_w + (size_t)L * EMBED * QKVC, bth, EMBED, QKVC);
        hgemm<1><<<dim3(QKVC / 128, MTOT / 128), 256>>>(
            MTOT, QKVC, EMBED, ln, bth, qkv, qkv_b + L * QKVC, nullptr);
        rel_tables_k<<<BH * NTOK, 64>>>(qkv, rph + L * RELT * HD,
                                        rpw + L * RELT * HD, relh, relw);
        flash_attn_k<<<dim3(16, BH), 256, sizeof(FlashSmem)>>>(
            qkv, relh, relw, attnout);
        wtrans_h<<<dim3(EMBED / 32, EMBED / 32), 256>>>(
            proj_w + (size_t)L * EMBED * EMBED, bth, EMBED, EMBED);
        hgemm<2><<<dim3(EMBED / 128, MTOT / 128), 256>>>(
            MTOT, EMBED, EMBED, attnout, bth, h, proj_b + L * EMBED, h);
        layernorm_h<<<MTOT, 256>>>(h, ln2_w + L * EMBED, ln2_b + L * EMBED, ln);
        wtrans_h<<<dim3(EMBED / 32, MLPD / 32), 256>>>(
            fc1_w + (size_t)L * EMBED * MLPD, bth, EMBED, MLPD);
        hgemm<3><<<dim3(MLPD / 128, MTOT / 128), 256>>>(
            MTOT, MLPD, EMBED, ln, bth, mlp, fc1_b + L * MLPD, nullptr);
        float* dst = (L == DEPTH - 1) ? out : h;
        wtrans_h<<<dim3(MLPD / 32, EMBED / 32), 256>>>(
            fc2_w + (size_t)L * MLPD * EMBED, bth, MLPD, EMBED);
        hgemm<2><<<dim3(EMBED / 128, MTOT / 128), 256>>>(
            MTOT, EMBED, MLPD, mlp, bth, dst, fc2_b + L * EMBED, h);
    }
}

// round 6
// speedup vs baseline: 1.3452x; 1.3452x over previous
#include <cuda_runtime.h>
#include <math.h>
#include <stdint.h>

// ---------------- problem constants ----------------
#define BATCH   4
#define NTOK    1024
#define EMBED   768
#define HEADS   12
#define HD      64
#define DEPTH   4
#define QKVC    2304
#define MLPD    3072
#define MTOT    4096
#define BH      48
#define RELT    63

// ---------------- scratch ----------------
__device__ float g_h[MTOT * EMBED];
__device__ float g_ln[MTOT * EMBED];
__device__ float g_qkv[MTOT * QKVC];
__device__ float g_attnout[MTOT * EMBED];
__device__ float g_mlp[MTOT * MLPD];
__device__ float g_relh[BH * NTOK * 32];
__device__ float g_relw[BH * NTOK * 32];
__device__ float g_col[MTOT * EMBED];
__device__ float g_wt[EMBED * EMBED];

// ---------------- helpers ----------------
__device__ __forceinline__ float gelu_exact(float x) {
    return 0.5f * x * (1.0f + erff(x * 0.70710678118654752440f));
}
__device__ __forceinline__ float blockSum256(float v, float* red) {
    const int tid = threadIdx.x;
    #pragma unroll
    for (int o = 16; o > 0; o >>= 1) v += __shfl_xor_sync(0xffffffffu, v, o);
    if ((tid & 31) == 0) red[tid >> 5] = v;
    __syncthreads();
    float t = 0.f;
    #pragma unroll
    for (int i = 0; i < 8; i++) t += red[i];
    return t;
}
__device__ __forceinline__ float rna_tf32(float x) {
    return __uint_as_float(__float_as_uint(x) + 0x1000u);
}
__device__ __forceinline__ float4 rna4(float4 v) {
    v.x = rna_tf32(v.x); v.y = rna_tf32(v.y);
    v.z = rna_tf32(v.z); v.w = rna_tf32(v.w);
    return v;
}
__device__ __forceinline__ void mma_tf32(float* d, const uint32_t* a,
                                         const uint32_t* b) {
    asm volatile(
        "mma.sync.aligned.m16n8k8.row.col.f32.tf32.tf32.f32 "
        "{%0,%1,%2,%3}, {%4,%5,%6,%7}, {%8,%9}, {%0,%1,%2,%3};\n"
        : "+f"(d[0]), "+f"(d[1]), "+f"(d[2]), "+f"(d[3])
        : "r"(a[0]), "r"(a[1]), "r"(a[2]), "r"(a[3]), "r"(b[0]), "r"(b[1]));
}

// ---------------- tf32 tensor-core GEMM, 128x128x16 tile, 8 warps ----------
template <int EPI>
__global__ void __launch_bounds__(256) mma_gemm(
    int M, int N, int K,
    const float* __restrict__ A, const float* __restrict__ B,
    float* __restrict__ C,
    const float* __restrict__ bias, const float* __restrict__ res)
{
    constexpr int BM = 128, BN = 128, BK = 16;
    __shared__ float As[2][BM][BK + 4];
    __shared__ float Bs[2][BK][BN + 8];

    const int tid = threadIdx.x;
    const int lane = tid & 31;
    const int wid = tid >> 5;
    const int wm = wid & 1;
    const int wn = wid >> 1;
    const int g = lane >> 2, tg = lane & 3;

    const float* Ab = A + (size_t)blockIdx.y * BM * K;
    const float* Bb = B + blockIdx.x * BN;

    float acc[4][4][4];
    #pragma unroll
    for (int i = 0; i < 4; i++)
        #pragma unroll
        for (int j = 0; j < 4; j++)
            #pragma unroll
            for (int r = 0; r < 4; r++) acc[i][j][r] = 0.f;

    const int aRow0 = tid >> 2;
    const int aC4   = tid & 3;
    const int bRow0 = tid >> 5;
    const int bC4   = tid & 31;

    float4 ra[2], rb[2];
    const int nIter = K / BK;

    #pragma unroll
    for (int p = 0; p < 2; p++) {
        ra[p] = *reinterpret_cast<const float4*>(
            Ab + (size_t)(aRow0 + p * 64) * K + aC4 * 4);
        rb[p] = *reinterpret_cast<const float4*>(
            Bb + (size_t)(bRow0 + p * 8) * N + bC4 * 4);
    }
    #pragma unroll
    for (int p = 0; p < 2; p++) {
        *reinterpret_cast<float4*>(&As[0][aRow0 + p * 64][aC4 * 4]) = rna4(ra[p]);
        *reinterpret_cast<float4*>(&Bs[0][bRow0 + p * 8][bC4 * 4]) = rna4(rb[p]);
    }
    __syncthreads();

    int buf = 0;
    for (int it = 0; it < nIter; ++it) {
        if (it + 1 < nIter) {
            const int k0 = (it + 1) * BK;
            #pragma unroll
            for (int p = 0; p < 2; p++) {
                ra[p] = *reinterpret_cast<const float4*>(
                    Ab + (size_t)(aRow0 + p * 64) * K + k0 + aC4 * 4);
                rb[p] = *reinterpret_cast<const float4*>(
                    Bb + (size_t)(k0 + bRow0 + p * 8) * N + bC4 * 4);
            }
        }
        #pragma unroll
        for (int kf = 0; kf < 2; kf++) {
            uint32_t af[4][4];
            uint32_t bf[4][2];
            #pragma unroll
            for (int mf = 0; mf < 4; mf++) {
                const int r = wm * 64 + mf * 16;
                af[mf][0] = __float_as_uint(As[buf][r + g][kf * 8 + tg]);
                af[mf][1] = __float_as_uint(As[buf][r + 8 + g][kf * 8 + tg]);
                af[mf][2] = __float_as_uint(As[buf][r + g][kf * 8 + tg + 4]);
                af[mf][3] = __float_as_uint(As[buf][r + 8 + g][kf * 8 + tg + 4]);
            }
            #pragma unroll
            for (int nf = 0; nf < 4; nf++) {
                const int c = wn * 32 + nf * 8;
                bf[nf][0] = __float_as_uint(Bs[buf][kf * 8 + tg][c + g]);
                bf[nf][1] = __float_as_uint(Bs[buf][kf * 8 + tg + 4][c + g]);
            }
            #pragma unroll
            for (int mf = 0; mf < 4; mf++)
                #pragma unroll
                for (int nf = 0; nf < 4; nf++)
                    mma_tf32(acc[mf][nf], af[mf], bf[nf]);
        }
        if (it + 1 < nIter) {
            #pragma unroll
            for (int p = 0; p < 2; p++) {
                *reinterpret_cast<float4*>(&As[buf ^ 1][aRow0 + p * 64][aC4 * 4]) =
                    rna4(ra[p]);
                *reinterpret_cast<float4*>(&Bs[buf ^ 1][bRow0 + p * 8][bC4 * 4]) =
                    rna4(rb[p]);
            }
        }
        __syncthreads();
        buf ^= 1;
    }

    #pragma unroll
    for (int mf = 0; mf < 4; mf++) {
        const int row0 = blockIdx.y * 128 + wm * 64 + mf * 16 + g;
        #pragma unroll
        for (int nf = 0; nf < 4; nf++) {
            const int col = blockIdx.x * 128 + wn * 32 + nf * 8 + tg * 2;
            #pragma unroll
            for (int half = 0; half < 2; half++) {
                const int m = row0 + half * 8;
                float c0 = acc[mf][nf][half * 2 + 0];
                float c1 = acc[mf][nf][half * 2 + 1];
                if (EPI == 1) {
                    c0 += bias[col]; c1 += bias[col + 1];
                } else if (EPI == 2) {
                    c0 += bias[col]     + res[(size_t)m * N + col];
                    c1 += bias[col + 1] + res[(size_t)m * N + col + 1];
                } else if (EPI == 3) {
                    c0 = gelu_exact(c0 + bias[col]);
                    c1 = gelu_exact(c1 + bias[col + 1]);
                } else if (EPI == 4) {
                    c0 += bias[col]     + res[(size_t)(m & (NTOK - 1)) * N + col];
                    c1 += bias[col + 1] + res[(size_t)(m & (NTOK - 1)) * N + col + 1];
                }
                *reinterpret_cast<float2*>(&C[(size_t)m * N + col]) =
                    make_float2(c0, c1);
            }
        }
    }
}

// ---------------- im2col ----------------
__global__ void __launch_bounds__(256) im2col_k(const float* __restrict__ x,
                                                float* __restrict__ col)
{
    int idx = blockIdx.x * 256 + threadIdx.x;
    int m = idx / EMBED, k = idx - m * EMBED;
    int b = m >> 10;
    int gy = (m >> 5) & 31, gx = m & 31;
    int ci = k >> 8;
    int ph = (k >> 4) & 15, pw = k & 15;
    col[idx] = x[(((size_t)b * 3 + ci) * 512 + gy * 16 + ph) * 512 + gx * 16 + pw];
}

__global__ void __launch_bounds__(256) transpose768_k(const float* __restrict__ w,
                                                      float* __restrict__ wt)
{
    int idx = blockIdx.x * 256 + threadIdx.x;
    int k = idx / EMBED, co = idx - k * EMBED;
    wt[idx] = w[(size_t)co * EMBED + k];
}

// ---------------- LayerNorm ----------------
__global__ void __launch_bounds__(256) layernorm_k(
    const float* __restrict__ in, const float* __restrict__ w,
    const float* __restrict__ b, float* __restrict__ out)
{
    __shared__ float red[8];
    const int tid = threadIdx.x;
    const float* p = in + (size_t)blockIdx.x * EMBED;
    float* q = out + (size_t)blockIdx.x * EMBED;
    float x0 = p[tid], x1 = p[tid + 256], x2 = p[tid + 512];
    float s  = blockSum256(x0 + x1 + x2, red);
    __syncthreads();
    float sq = blockSum256(x0 * x0 + x1 * x1 + x2 * x2, red);
    float mean = s * (1.f / 768.f);
    float var = sq * (1.f / 768.f) - mean * mean;
    float rs = rsqrtf(var + 1e-5f);
    q[tid]       = (x0 - mean) * rs * w[tid]       + b[tid];
    q[tid + 256] = (x1 - mean) * rs * w[tid + 256] + b[tid + 256];
    q[tid + 512] = (x2 - mean) * rs * w[tid + 512] + b[tid + 512];
}

// ---------------- rel-pos bias tables ----------------
__global__ void __launch_bounds__(64) rel_tables_k(
    const float* __restrict__ qkv, const float* __restrict__ rph,
    const float* __restrict__ rpw, float* __restrict__ relh,
    float* __restrict__ relw)
{
    __shared__ float qv[HD];
    const int bq = blockIdx.x;
    const int bh = bq >> 10, q = bq & 1023;
    const int b = bh / HEADS, head = bh % HEADS;
    const int hq = q >> 5, wq = q & 31;
    const int tid = threadIdx.x;
    qv[tid] = qkv[((size_t)(b * NTOK + q)) * QKVC + head * HD + tid];
    __syncthreads();
    const int kidx = tid & 31;
    const float* r;
    float* out;
    if (tid < 32) { r = rph + (hq - kidx + 31) * HD; out = relh; }
    else          { r = rpw + (wq - kidx + 31) * HD; out = relw; }
    float s = 0.f;
    #pragma unroll
    for (int d = 0; d < HD; d++) s = fmaf(qv[d], r[d], s);
    out[((size_t)bh * NTOK + q) * 32 + kidx] = s;
}

// ---------------- fused flash attention (tf32 MMA, fast exp) ---------------
struct FlashSmem {
    float K[64][68];
    float V[64][72];
    float S[64][68];
    float rh[64][32];
    float rw[64][32];
    float mrow[64];
    float lrow[64];
    float arow[64];
};

__global__ void __launch_bounds__(256) flash_attn_k(
    const float* __restrict__ qkv, const float* __restrict__ relh,
    const float* __restrict__ relw, float* __restrict__ outbuf)
{
    extern __shared__ char smraw[];
    FlashSmem& sm = *reinterpret_cast<FlashSmem*>(smraw);
    const int qt = blockIdx.x, bh = blockIdx.y;
    const int b = bh / HEADS, head = bh % HEADS;
    const float* Qg = qkv + (size_t)b * NTOK * QKVC + head * HD;
    const float* Kg = Qg + EMBED;
    const float* Vg = Qg + 2 * EMBED;
    const int tid = threadIdx.x, lane = tid & 31, wid = tid >> 5;
    const int wm = wid & 3, wn = wid >> 2;
    const int g = lane >> 2, tg = lane & 3;

    for (int i = tid; i < 64 * 32; i += 256) {
        int r = i >> 5, c = i & 31;
        sm.rh[r][c] = relh[((size_t)bh * NTOK + qt * 64 + r) * 32 + c];
        sm.rw[r][c] = relw[((size_t)bh * NTOK + qt * 64 + r) * 32 + c];
    }
    if (tid < 64) { sm.mrow[tid] = -INFINITY; sm.lrow[tid] = 0.f; }

    const int sKey = tid >> 4;
    const int sD4  = (tid & 15) * 4;
    #pragma unroll
    for (int r = 0; r < 4; r++) {
        float4 v = *reinterpret_cast<const float4*>(
            Qg + (size_t)(qt * 64 + sKey + 16 * r) * QKVC + sD4);
        *reinterpret_cast<float4*>(&sm.S[sKey + 16 * r][sD4]) = rna4(v);
    }
    __syncthreads();
    uint32_t aq[8][4];
    #pragma unroll
    for (int kf = 0; kf < 8; kf++) {
        aq[kf][0] = __float_as_uint(sm.S[wm * 16 + g][kf * 8 + tg]);
        aq[kf][1] = __float_as_uint(sm.S[wm * 16 + 8 + g][kf * 8 + tg]);
        aq[kf][2] = __float_as_uint(sm.S[wm * 16 + g][kf * 8 + tg + 4]);
        aq[kf][3] = __float_as_uint(sm.S[wm * 16 + 8 + g][kf * 8 + tg + 4]);
    }

    float oacc[4][4];
    #pragma unroll
    for (int i = 0; i < 4; i++)
        #pragma unroll
        for (int j = 0; j < 4; j++) oacc[i][j] = 0.f;

    float4 pk[4], pv[4];
    #pragma unroll
    for (int r = 0; r < 4; r++) {
        pk[r] = *reinterpret_cast<const float4*>(
            Kg + (size_t)(sKey + 16 * r) * QKVC + sD4);
        pv[r] = *reinterpret_cast<const float4*>(
            Vg + (size_t)(sKey + 16 * r) * QKVC + sD4);
    }

    for (int t = 0; t < 16; t++) {
        __syncthreads();
        #pragma unroll
        for (int r = 0; r < 4; r++) {
            *reinterpret_cast<float4*>(&sm.K[sKey + 16 * r][sD4]) = rna4(pk[r]);
            *reinterpret_cast<float4*>(&sm.V[sKey + 16 * r][sD4]) = rna4(pv[r]);
        }
        __syncthreads();
        if (t + 1 < 16) {
            #pragma unroll
            for (int r = 0; r < 4; r++) {
                pk[r] = *reinterpret_cast<const float4*>(
                    Kg + (size_t)((t + 1) * 64 + sKey + 16 * r) * QKVC + sD4);
                pv[r] = *reinterpret_cast<const float4*>(
                    Vg + (size_t)((t + 1) * 64 + sKey + 16 * r) * QKVC + sD4);
            }
        }
        float sacc[4][4];
        #pragma unroll
        for (int i = 0; i < 4; i++)
            #pragma unroll
            for (int j = 0; j < 4; j++) sacc[i][j] = 0.f;
        #pragma unroll
        for (int kf = 0; kf < 8; kf++) {
            uint32_t bf[4][2];
            #pragma unroll
            for (int nf = 0; nf < 4; nf++) {
                const int c = wn * 32 + nf * 8;
                bf[nf][0] = __float_as_uint(sm.K[c + g][kf * 8 + tg]);
                bf[nf][1] = __float_as_uint(sm.K[c + g][kf * 8 + tg + 4]);
            }
            #pragma unroll
            for (int nf = 0; nf < 4; nf++) mma_tf32(sacc[nf], aq[kf], bf[nf]);
        }
        #pragma unroll
        for (int nf = 0; nf < 4; nf++) {
            const int c = wn * 32 + nf * 8 + tg * 2;
            sm.S[wm * 16 + g][c]         = sacc[nf][0] * 0.125f;
            sm.S[wm * 16 + g][c + 1]     = sacc[nf][1] * 0.125f;
            sm.S[wm * 16 + 8 + g][c]     = sacc[nf][2] * 0.125f;
            sm.S[wm * 16 + 8 + g][c + 1] = sacc[nf][3] * 0.125f;
        }
        __syncthreads();
        {
            const int row = tid >> 2, part = tid & 3;
            const float mo = sm.mrow[row];
            const float rhv = sm.rh[row][(t << 1) + (part >> 1)];
            float vals[16];
            float tmax = -INFINITY;
            #pragma unroll
            for (int j = 0; j < 16; j++) {
                float s = sm.S[row][part * 16 + j] + rhv
                        + sm.rw[row][(part & 1) * 16 + j];
                vals[j] = s;
                tmax = fmaxf(tmax, s);
            }
            tmax = fmaxf(tmax, __shfl_xor_sync(0xffffffffu, tmax, 1));
            tmax = fmaxf(tmax, __shfl_xor_sync(0xffffffffu, tmax, 2));
            const float nm = fmaxf(mo, tmax);
            float lsum = 0.f;
            #pragma unroll
            for (int j = 0; j < 16; j++) {
                float p = __expf(vals[j] - nm);
                lsum += p;
                sm.S[row][part * 16 + j] = rna_tf32(p);
            }
            lsum += __shfl_xor_sync(0xffffffffu, lsum, 1);
            lsum += __shfl_xor_sync(0xffffffffu, lsum, 2);
            if (part == 0) {
                const float alpha = __expf(mo - nm);
                sm.mrow[row] = nm;
                sm.lrow[row] = sm.lrow[row] * alpha + lsum;
                sm.arow[row] = alpha;
            }
        }
        __syncthreads();
        const float a0 = sm.arow[wm * 16 + g];
        const float a1 = sm.arow[wm * 16 + 8 + g];
        #pragma unroll
        for (int nf = 0; nf < 4; nf++) {
            oacc[nf][0] *= a0; oacc[nf][1] *= a0;
            oacc[nf][2] *= a1; oacc[nf][3] *= a1;
        }
        #pragma unroll
        for (int kf = 0; kf < 8; kf++) {
            uint32_t ap[4];
            ap[0] = __float_as_uint(sm.S[wm * 16 + g][kf * 8 + tg]);
            ap[1] = __float_as_uint(sm.S[wm * 16 + 8 + g][kf * 8 + tg]);
            ap[2] = __float_as_uint(sm.S[wm * 16 + g][kf * 8 + tg + 4]);
            ap[3] = __float_as_uint(sm.S[wm * 16 + 8 + g][kf * 8 + tg + 4]);
            uint32_t bf[4][2];
            #pragma unroll
            for (int nf = 0; nf < 4; nf++) {
                const int c = wn * 32 + nf * 8;
                bf[nf][0] = __float_as_uint(sm.V[kf * 8 + tg][c + g]);
                bf[nf][1] = __float_as_uint(sm.V[kf * 8 + tg + 4][c + g]);
            }
            #pragma unroll
            for (int nf = 0; nf < 4; nf++) mma_tf32(oacc[nf], ap, bf[nf]);
        }
    }
    __syncthreads();
    const float li0 = 1.f / sm.lrow[wm * 16 + g];
    const float li1 = 1.f / sm.lrow[wm * 16 + 8 + g];
    const int m0 = qt * 64 + wm * 16 + g;
    #pragma unroll
    for (int nf = 0; nf < 4; nf++) {
        const int d = wn * 32 + nf * 8 + tg * 2;
        float* dst0 = outbuf + ((size_t)b * NTOK + m0) * EMBED + head * HD + d;
        float* dst1 = dst0 + 8 * EMBED;
        *reinterpret_cast<float2*>(dst0) =
            make_float2(oacc[nf][0] * li0, oacc[nf][1] * li0);
        *reinterpret_cast<float2*>(dst1) =
            make_float2(oacc[nf][2] * li1, oacc[nf][3] * li1);
    }
}

// ---------------- host launcher ----------------
extern "C" void kernel_launch(void* const* d_in, const int* in_sizes, int n_in,
                              void* d_out, int out_size)
{
    const float* x       = (const float*)d_in[0];
    const float* conv_w  = (const float*)d_in[1];
    const float* conv_b  = (const float*)d_in[2];
    const float* pos     = (const float*)d_in[3];
    const float* ln1_w   = (const float*)d_in[4];
    const float* ln1_b   = (const float*)d_in[5];
    const float* qkv_w   = (const float*)d_in[6];
    const float* qkv_b   = (const float*)d_in[7];
    const float* proj_w  = (const float*)d_in[8];
    const float* proj_b  = (const float*)d_in[9];
    const float* rph     = (const float*)d_in[10];
    const float* rpw     = (const float*)d_in[11];
    const float* ln2_w   = (const float*)d_in[12];
    const float* ln2_b   = (const float*)d_in[13];
    const float* fc1_w   = (const float*)d_in[14];
    const float* fc1_b   = (const float*)d_in[15];
    const float* fc2_w   = (const float*)d_in[16];
    const float* fc2_b   = (const float*)d_in[17];
    float* out = (float*)d_out;

    float *h, *ln, *qkv, *attnout, *mlp, *relh, *relw, *col, *wt;
    cudaGetSymbolAddress((void**)&h, g_h);
    cudaGetSymbolAddress((void**)&ln, g_ln);
    cudaGetSymbolAddress((void**)&qkv, g_qkv);
    cudaGetSymbolAddress((void**)&attnout, g_attnout);
    cudaGetSymbolAddress((void**)&mlp, g_mlp);
    cudaGetSymbolAddress((void**)&relh, g_relh);
    cudaGetSymbolAddress((void**)&relw, g_relw);
    cudaGetSymbolAddress((void**)&col, g_col);
    cudaGetSymbolAddress((void**)&wt, g_wt);

    cudaFuncSetAttribute(flash_attn_k,
                         cudaFuncAttributeMaxDynamicSharedMemorySize,
                         (int)sizeof(FlashSmem));

    transpose768_k<<<(EMBED * EMBED) / 256, 256>>>(conv_w, wt);
    im2col_k<<<(MTOT * EMBED) / 256, 256>>>(x, col);
    mma_gemm<4><<<dim3(EMBED / 128, MTOT / 128), 256>>>(
        MTOT, EMBED, EMBED, col, wt, h, conv_b, pos);

    for (int L = 0; L < DEPTH; L++) {
        layernorm_k<<<MTOT, 256>>>(h, ln1_w + L * EMBED, ln1_b + L * EMBED, ln);
        mma_gemm<1><<<dim3(QKVC / 128, MTOT / 128), 256>>>(
            MTOT, QKVC, EMBED, ln, qkv_w + (size_t)L * EMBED * QKVC, qkv,
            qkv_b + L * QKVC, nullptr);
        rel_tables_k<<<BH * NTOK, 64>>>(qkv, rph + L * RELT * HD,
                                        rpw + L * RELT * HD, relh, relw);
        flash_attn_k<<<dim3(16, BH), 256, sizeof(FlashSmem)>>>(
            qkv, relh, relw, attnout);
        mma_gemm<2><<<dim3(EMBED / 128, MTOT / 128), 256>>>(
            MTOT, EMBED, EMBED, attnout, proj_w + (size_t)L * EMBED * EMBED, h,
            proj_b + L * EMBED, h);
        layernorm_k<<<MTOT, 256>>>(h, ln2_w + L * EMBED, ln2_b + L * EMBED, ln);
        mma_gemm<3><<<dim3(MLPD / 128, MTOT / 128), 256>>>(
            MTOT, MLPD, EMBED, ln, fc1_w + (size_t)L * EMBED * MLPD, mlp,
            fc1_b + L * MLPD, nullptr);
        float* dst = (L == DEPTH - 1) ? out : h;
        mma_gemm<2><<<dim3(EMBED / 128, MTOT / 128), 256>>>(
            MTOT, EMBED, MLPD, mlp, fc2_w + (size_t)L * MLPD * EMBED, dst,
            fc2_b + L * EMBED, h);
    }
}